// round 15
// baseline (speedup 1.0000x reference)
#include <cuda_runtime.h>
#include <cuda_fp16.h>

#define Bq   8
#define Tq   4096
#define DINq 1024
#define DMq  256
#define NCq  157

// ---------------------------------------------------------------------------
// Activations: single fp16 plane, [B, T, C] (K-major for MMA B operand).
// Weights: fp16 hi + lo planes (W = hi + lo, exact to 2^-24).
// GEMM computes W_hi*B + W_lo*B = W*B exactly on fp16-quantized activations.
// ---------------------------------------------------------------------------
__device__ __half g_x  [Bq * Tq * DINq];
__device__ __half g_o  [Bq * Tq * DMq];
__device__ __half g_qkv[Bq * Tq * 3 * DMq];
__device__ __half g_h  [Bq * Tq * DMq];

// Weights: b0w(256x1024), per layer wq|wk|wv|bw (each 256x256), b6w(157x256)
#define W_B0    0
#define W_L0    262144
#define W_PERL  (4 * 65536)
#define W_B6    (262144 + 5 * W_PERL)
#define W_TOTAL (W_B6 + NCq * DMq)
__device__ __half g_wh[W_TOTAL];
__device__ __half g_wl[W_TOTAL];

// ---------------------------------------------------------------------------
// Helpers
// ---------------------------------------------------------------------------
__device__ __forceinline__ unsigned smem_u32(const void* p) {
    unsigned a;
    asm("{ .reg .u64 t; cvta.to.shared.u64 t, %1; cvt.u32.u64 %0, t; }" : "=r"(a) : "l"(p));
    return a;
}
__device__ __forceinline__ void splitw(float v, __half& h, __half& l) {
    h = __float2half_rn(v);
    l = __float2half_rn(v - __half2float(h));
}
__device__ __forceinline__ void ldmat4(unsigned (&r)[4], unsigned addr) {
    asm volatile("ldmatrix.sync.aligned.m8n8.x4.shared.b16 {%0,%1,%2,%3}, [%4];"
                 : "=r"(r[0]), "=r"(r[1]), "=r"(r[2]), "=r"(r[3]) : "r"(addr));
}
__device__ __forceinline__ void mma16816(float (&c)[4], const unsigned (&a)[4],
                                         unsigned b0, unsigned b1) {
    asm volatile(
        "mma.sync.aligned.m16n8k16.row.col.f32.f16.f16.f32 "
        "{%0,%1,%2,%3}, {%4,%5,%6,%7}, {%8,%9}, {%0,%1,%2,%3};"
        : "+f"(c[0]), "+f"(c[1]), "+f"(c[2]), "+f"(c[3])
        : "r"(a[0]), "r"(a[1]), "r"(a[2]), "r"(a[3]), "r"(b0), "r"(b1));
}
// L1-bypass async copy (tiles have zero L1 reuse)
__device__ __forceinline__ void cp16(unsigned saddr, const void* gaddr, int srcsz) {
    asm volatile("cp.async.cg.shared.global [%0], [%1], 16, %2;"
                 :: "r"(saddr), "l"(gaddr), "r"(srcsz) : "memory");
}
#define CP_COMMIT() asm volatile("cp.async.commit_group;" ::: "memory")
#define CP_WAIT1()  asm volatile("cp.async.wait_group 1;" ::: "memory")

// ---------------------------------------------------------------------------
// GEMM: D[o,t] = sum_i W[o,i] * Act[b,t,i]   (split-fp16 x2, mma.sync)
// Block 128(M=o) x 128(N=t), K-SUPERCHUNK 64, 256 threads (8 warps, 4m x 2n),
// warp tile 32x64. 2 superstages x 48KB, single commit per super,
// 64B stride + XOR swizzle.
// Mainloop hazard fix: all B fragments of a kk-step are register-resident;
// 16 hi-MMAs (16 distinct accs) are issued before the 16 lo-MMAs, pushing the
// per-accumulator reuse distance from 4 to 16 issue slots (covers HMMA lat).
// Per-acc FMA order (hi then lo per kk) is unchanged -> bit-identical result.
// EPI: 0 plain -> fp16 [b,t,o] stride OSTR      (qkv)
//      1 +bias -> fp16                          (b0)
//      2 (resid+D+bias)*mask -> fp16            (bottleneck)
//      3 (D+bias)*mask -> fp32 [b,o,t]          (final)
// ---------------------------------------------------------------------------
#define PART     16384              // one plane per super (two 8K k-halves)
#define SSTAGE   49152              // W_hi | W_lo | B
#define SMEM_TOT 98304              // 2 superstages

template <int EPI, int KTOT, int OROWS, int OSTR>
__global__ void __launch_bounds__(256, 2)
gemm_mma(const __half* __restrict__ Whi, const __half* __restrict__ Wlo,
         const __half* __restrict__ Act,
         const float* __restrict__ bias, const float* __restrict__ mask,
         const __half* __restrict__ Resid,
         __half* __restrict__ Out, float* __restrict__ OF)
{
    extern __shared__ char smem[];
    const unsigned sb = smem_u32(smem);
    const int tid  = threadIdx.x;
    const int lane = tid & 31, wid = tid >> 5;
    const int bT = blockIdx.x * 128;
    const int bO = blockIdx.y * 128;
    const int b  = blockIdx.z;
    const int m0 = (wid & 3) * 32;
    const int n0 = (wid >> 2) * 64;

    constexpr bool GUARDA = (OROWS & 127) != 0;
    constexpr int NSUP = KTOT / 64;

    const __half* Bg = Act + ((size_t)b * Tq + bT) * KTOT;

    // ldmatrix per-thread swizzled offsets (64B stride, chunk ^= (row>>1)&3)
    const int raA  = lane & 15;
    const int xorA = (raA >> 1) & 3;
    const int laA[2] = { raA * 64 + ((((lane >> 4)    ) ^ xorA) << 4),
                         raA * 64 + ((((lane >> 4) + 2) ^ xorA) << 4) };
    const int matv = lane >> 3;
    const int rbB  = (lane & 7) + ((matv >> 1) * 8);
    const int xorB = (rbB >> 1) & 3;
    const int lbB[2] = { rbB * 64 + ((((matv & 1)    ) ^ xorB) << 4),
                         rbB * 64 + ((((matv & 1) + 2) ^ xorB) << 4) };

    float acc[2][8][4];
#pragma unroll
    for (int i = 0; i < 2; i++)
#pragma unroll
        for (int j = 0; j < 8; j++)
#pragma unroll
            for (int l = 0; l < 4; l++) acc[i][j][l] = 0.f;

    // ---- superchunk async issue: 12 cp16/thread, ONE commit group ----
    auto issue = [&](int s, int stg) {
        if (s < NSUP) {
            const int k0 = s * 64;
            const unsigned st = sb + stg * SSTAGE;
#pragma unroll
            for (int i = 0; i < 12; i++) {
                const int task = i * 256 + tid;          // 0..3071
                const int plane = task >> 10;            // 0=W.hi 1=W.lo 2=B
                const int q2 = task & 1023;
                const int kh = q2 >> 9;                  // k-half (0/1)
                const int q  = q2 & 511;
                const int row = q >> 2, c = q & 3;
                const unsigned soff = (unsigned)(plane * PART + kh * 8192 +
                                                 row * 64 + ((c ^ ((row >> 1) & 3)) << 4));
                const int kcol = k0 + kh * 32 + c * 8;
                if (plane < 2) {
                    int asz = 16;
                    size_t aoff = (size_t)(bO + row) * KTOT + kcol;
                    if (GUARDA && (bO + row >= OROWS)) { asz = 0; aoff = 0; }
                    cp16(st + soff, (plane ? Wlo : Whi) + aoff, asz);
                } else {
                    cp16(st + soff, Bg + (size_t)row * KTOT + kcol, 16);
                }
            }
        }
        CP_COMMIT();
    };

    issue(0, 0);
    issue(1, 1);

    int cs = 0;
#pragma unroll 1
    for (int s = 0; s < NSUP; s++) {
        CP_WAIT1();
        __syncthreads();

        const unsigned base = sb + cs * SSTAGE;

#pragma unroll
        for (int kk2 = 0; kk2 < 4; kk2++) {
            const int half = kk2 >> 1, kkk = kk2 & 1;
            const unsigned A0_ = base + half * 8192;
            const unsigned A1_ = A0_ + PART;
            const unsigned B_  = A0_ + 2 * PART;

            // ---- load ALL fragments for this kk-step first ----
            unsigned ah[2][4], al[2][4], bu[4][4];
            ldmat4(ah[0], A0_ + (m0     ) * 64 + laA[kkk]);
            ldmat4(ah[1], A0_ + (m0 + 16) * 64 + laA[kkk]);
            ldmat4(al[0], A1_ + (m0     ) * 64 + laA[kkk]);
            ldmat4(al[1], A1_ + (m0 + 16) * 64 + laA[kkk]);
#pragma unroll
            for (int nt2 = 0; nt2 < 4; nt2++)
                ldmat4(bu[nt2], B_ + (n0 + nt2 * 16) * 64 + lbB[kkk]);

            // ---- 16 hi-MMAs: 16 distinct accumulators ----
#pragma unroll
            for (int nt2 = 0; nt2 < 4; nt2++) {
                mma16816(acc[0][nt2 * 2 + 0], ah[0], bu[nt2][0], bu[nt2][1]);
                mma16816(acc[0][nt2 * 2 + 1], ah[0], bu[nt2][2], bu[nt2][3]);
                mma16816(acc[1][nt2 * 2 + 0], ah[1], bu[nt2][0], bu[nt2][1]);
                mma16816(acc[1][nt2 * 2 + 1], ah[1], bu[nt2][2], bu[nt2][3]);
            }
            // ---- 16 lo-MMAs: reuse distance 16 vs the hi write ----
#pragma unroll
            for (int nt2 = 0; nt2 < 4; nt2++) {
                mma16816(acc[0][nt2 * 2 + 0], al[0], bu[nt2][0], bu[nt2][1]);
                mma16816(acc[0][nt2 * 2 + 1], al[0], bu[nt2][2], bu[nt2][3]);
                mma16816(acc[1][nt2 * 2 + 0], al[1], bu[nt2][0], bu[nt2][1]);
                mma16816(acc[1][nt2 * 2 + 1], al[1], bu[nt2][2], bu[nt2][3]);
            }
        }

        __syncthreads();           // all warps done reading stage cs
        issue(s + 2, cs);          // refill it
        cs ^= 1;
    }

    // ---- epilogue ----
    const int g = lane >> 2, tig = lane & 3;
#pragma unroll
    for (int mi = 0; mi < 2; mi++) {
#pragma unroll
        for (int pr = 0; pr < 2; pr++) {
            const int o = bO + m0 + mi * 16 + g + pr * 8;
            float bs = 0.f;
            if (EPI >= 1) bs = (!GUARDA || o < OROWS) ? bias[o] : 0.f;
#pragma unroll
            for (int nt = 0; nt < 8; nt++) {
                const int t = bT + n0 + nt * 8 + 2 * tig;
                float v0 = acc[mi][nt][pr * 2 + 0] + bs;
                float v1 = acc[mi][nt][pr * 2 + 1] + bs;
                if (EPI == 3) {
                    if (!GUARDA || o < OROWS) {
                        const float mk0 = mask[(size_t)b * Tq + t];
                        const float mk1 = mask[(size_t)b * Tq + t + 1];
                        *(float2*)(OF + ((size_t)b * OROWS + o) * Tq + t) =
                            make_float2(v0 * mk0, v1 * mk1);
                    }
                } else {
                    const size_t i0 = ((size_t)b * Tq + t) * OSTR + o;
                    if (EPI == 2) {
                        const float mk0 = mask[(size_t)b * Tq + t];
                        const float mk1 = mask[(size_t)b * Tq + t + 1];
                        v0 = (__half2float(Resid[i0])        + v0) * mk0;
                        v1 = (__half2float(Resid[i0 + OSTR]) + v1) * mk1;
                    }
                    Out[i0]        = __float2half_rn(v0);
                    Out[i0 + OSTR] = __float2half_rn(v1);
                }
            }
        }
    }
}

// ---------------------------------------------------------------------------
// x transpose: [B, DIN, T] fp32 -> [B, T, DIN] fp16
// ---------------------------------------------------------------------------
__global__ __launch_bounds__(256)
void xpose_kernel(const float* __restrict__ x, __half* __restrict__ xo)
{
    __shared__ float s[32][33];
    const int t0 = blockIdx.x * 32, i0 = blockIdx.y * 32, b = blockIdx.z;
    const int tx = threadIdx.x & 31, ty = threadIdx.x >> 5;
    const float* xb = x + (size_t)b * DINq * Tq;
#pragma unroll
    for (int kk = 0; kk < 4; kk++)
        s[ty + 8 * kk][tx] = xb[(size_t)(i0 + ty + 8 * kk) * Tq + t0 + tx];
    __syncthreads();
#pragma unroll
    for (int kk = 0; kk < 4; kk++) {
        const size_t idx = ((size_t)b * Tq + t0 + ty + 8 * kk) * DINq + i0 + tx;
        xo[idx] = __float2half_rn(s[tx][ty + 8 * kk]);
    }
}

// ---------------------------------------------------------------------------
// Weight split: 22 fp32 matrices -> fp16 hi/lo
// ---------------------------------------------------------------------------
struct WPtrs { const float* p[22]; };

__global__ __launch_bounds__(256)
void convw_kernel(WPtrs wp, __half* __restrict__ wh, __half* __restrict__ wl)
{
    const int idx = blockIdx.x * 256 + threadIdx.x;
    int off = 0;
#pragma unroll
    for (int m = 0; m < 22; m++) {
        const int sz = (m == 0) ? 262144 : ((m == 21) ? NCq * DMq : 65536);
        if (idx < off + sz) {
            __half h, l;
            splitw(wp.p[m][idx - off], h, l);
            wh[idx] = h; wl[idx] = l;
            return;
        }
        off += sz;
    }
}

// ---------------------------------------------------------------------------
// Dilated 3-tap softmax attention + ReLU on fp16 qkv [B,T,768]
// ---------------------------------------------------------------------------
__device__ __forceinline__ void load4h(const __half* __restrict__ p, size_t e, float (&o)[4])
{
    const __half2 a = *(const __half2*)(p + e);
    const __half2 c = *(const __half2*)(p + e + 2);
    o[0] = __low2float(a); o[1] = __high2float(a);
    o[2] = __low2float(c); o[3] = __high2float(c);
}

__device__ __forceinline__ float attn1(float q, float k0, float k1, float k2,
                                       float v0, float v1, float v2)
{
    const float s0 = q * k0, s1 = q * k1, s2 = q * k2;
    const float mx = fmaxf(s0, fmaxf(s1, s2));
    const float e0 = __expf(s0 - mx), e1 = __expf(s1 - mx), e2 = __expf(s2 - mx);
    return fmaxf((e0 * v0 + e1 * v1 + e2 * v2) / (e0 + e1 + e2), 0.f);
}

__global__ __launch_bounds__(256)
void attn_kernel(const __half* __restrict__ qkv, __half* __restrict__ hout, int d)
{
    const size_t gid = (size_t)blockIdx.x * 256 + threadIdx.x;
    const int c4 = (int)(gid & 63);
    const int t  = (int)((gid >> 6) & (Tq - 1));
    const int b  = (int)(gid >> 18);
    const size_t rq = ((size_t)b * Tq + t) * 768 + c4 * 4;
    const long long off = (long long)d * 768;

    float q[4], k1[4], v1[4];
    load4h(qkv, rq,       q);
    load4h(qkv, rq + 256, k1);
    load4h(qkv, rq + 512, v1);
    float k0[4] = {0, 0, 0, 0}, v0[4] = {0, 0, 0, 0};
    float k2[4] = {0, 0, 0, 0}, v2[4] = {0, 0, 0, 0};
    if (t - d >= 0) { load4h(qkv, rq + 256 - off, k0); load4h(qkv, rq + 512 - off, v0); }
    if (t + d < Tq) { load4h(qkv, rq + 256 + off, k2); load4h(qkv, rq + 512 + off, v2); }

    const size_t e = ((size_t)b * Tq + t) * DMq + c4 * 4;
    const __half2 p0 = __floats2half2_rn(
        attn1(q[0], k0[0], k1[0], k2[0], v0[0], v1[0], v2[0]),
        attn1(q[1], k0[1], k1[1], k2[1], v0[1], v1[1], v2[1]));
    const __half2 p1 = __floats2half2_rn(
        attn1(q[2], k0[2], k1[2], k2[2], v0[2], v1[2], v2[2]),
        attn1(q[3], k0[3], k1[3], k2[3], v0[3], v1[3], v2[3]));
    uint2 w;
    w.x = *(const unsigned*)&p0;
    w.y = *(const unsigned*)&p1;
    *(uint2*)(hout + e) = w;
}

// ---------------------------------------------------------------------------
// Launch: batch split B=8 -> 4 streams x 2 batches (fork-join capture pattern)
// ---------------------------------------------------------------------------
#define NSTR 4

extern "C" void kernel_launch(void* const* d_in, const int* in_sizes, int n_in,
                              void* d_out, int out_size)
{
    const float* x    = (const float*)d_in[0];
    const float* mask = (const float*)d_in[1];
    const float* b0b  = (const float*)d_in[3];
    const float* b6b  = (const float*)d_in[30];

    __half *xb, *ob, *qkvb, *hb, *wh, *wl;
    cudaGetSymbolAddress((void**)&xb,   g_x);
    cudaGetSymbolAddress((void**)&ob,   g_o);
    cudaGetSymbolAddress((void**)&qkvb, g_qkv);
    cudaGetSymbolAddress((void**)&hb,   g_h);
    cudaGetSymbolAddress((void**)&wh,   g_wh);
    cudaGetSymbolAddress((void**)&wl,   g_wl);

    cudaFuncSetAttribute(gemm_mma<1, DINq, DMq, DMq>,        cudaFuncAttributeMaxDynamicSharedMemorySize, SMEM_TOT);
    cudaFuncSetAttribute(gemm_mma<0, DMq, 3 * DMq, 3 * DMq>, cudaFuncAttributeMaxDynamicSharedMemorySize, SMEM_TOT);
    cudaFuncSetAttribute(gemm_mma<2, DMq, DMq, DMq>,         cudaFuncAttributeMaxDynamicSharedMemorySize, SMEM_TOT);
    cudaFuncSetAttribute(gemm_mma<3, DMq, NCq, DMq>,         cudaFuncAttributeMaxDynamicSharedMemorySize, SMEM_TOT);

    // split weights (shared by all streams)
    WPtrs wp;
    wp.p[0] = (const float*)d_in[2];
    for (int l = 0; l < 5; l++) {
        wp.p[1 + 4 * l + 0] = (const float*)d_in[4 + 5 * l + 0];
        wp.p[1 + 4 * l + 1] = (const float*)d_in[4 + 5 * l + 1];
        wp.p[1 + 4 * l + 2] = (const float*)d_in[4 + 5 * l + 2];
        wp.p[1 + 4 * l + 3] = (const float*)d_in[4 + 5 * l + 3];
    }
    wp.p[21] = (const float*)d_in[29];
    convw_kernel<<<W_TOTAL / 256, 256>>>(wp, wh, wl);

    // fork worker streams off the main (capture) stream
    cudaStream_t st[NSTR];
    cudaEvent_t ev_fork, ev_join[NSTR];
    for (int s = 0; s < NSTR; s++) cudaStreamCreateWithFlags(&st[s], cudaStreamNonBlocking);
    cudaEventCreateWithFlags(&ev_fork, cudaEventDisableTiming);
    for (int s = 0; s < NSTR; s++) cudaEventCreateWithFlags(&ev_join[s], cudaEventDisableTiming);
    cudaEventRecord(ev_fork, 0);
    for (int s = 0; s < NSTR; s++) cudaStreamWaitEvent(st[s], ev_fork, 0);

    const int dils[5] = {1, 2, 4, 8, 16};
    const int HB = Bq / NSTR;   // 2 batches per stream

    for (int s = 0; s < NSTR; s++) {
        cudaStream_t S = st[s];
        const size_t b0 = (size_t)s * HB;

        const float* x_    = x    + b0 * DINq * Tq;
        const float* mask_ = mask + b0 * Tq;
        __half*      xb_   = xb   + b0 * Tq * DINq;
        __half*      ob_   = ob   + b0 * Tq * DMq;
        __half*      qk_   = qkvb + b0 * Tq * 3 * DMq;
        __half*      hb_   = hb   + b0 * Tq * DMq;
        float*       of_   = (float*)d_out + b0 * NCq * Tq;

        const dim3 thr(256);
        const dim3 g_xp (Tq / 32, DINq / 32, HB);
        const dim3 g_dm (Tq / 128, DMq / 128, HB);
        const dim3 g_qkv(Tq / 128, 3 * DMq / 128, HB);
        const dim3 g_nc (Tq / 128, (NCq + 127) / 128, HB);
        const int  g_at = (HB * Tq * 64) / 256;

        xpose_kernel<<<g_xp, thr, 0, S>>>(x_, xb_);

        gemm_mma<1, DINq, DMq, DMq><<<g_dm, thr, SMEM_TOT, S>>>(
            wh + W_B0, wl + W_B0, xb_, b0b, nullptr, nullptr, ob_, nullptr);

        for (int l = 0; l < 5; l++) {
            const float* bb = (const float*)d_in[4 + 5 * l + 4];
            const int wqkv = W_L0 + l * W_PERL;
            const int bw   = wqkv + 3 * 65536;

            gemm_mma<0, DMq, 3 * DMq, 3 * DMq><<<g_qkv, thr, SMEM_TOT, S>>>(
                wh + wqkv, wl + wqkv, ob_, nullptr, nullptr, nullptr, qk_, nullptr);

            attn_kernel<<<g_at, thr, 0, S>>>(qk_, hb_, dils[l]);

            gemm_mma<2, DMq, DMq, DMq><<<g_dm, thr, SMEM_TOT, S>>>(
                wh + bw, wl + bw, hb_, bb, mask_, ob_, ob_, nullptr);
        }

        gemm_mma<3, DMq, NCq, DMq><<<g_nc, thr, SMEM_TOT, S>>>(
            wh + W_B6, wl + W_B6, ob_, b6b, mask_, nullptr, nullptr, of_);
    }

    // join all streams back into the main stream
    for (int s = 0; s < NSTR; s++) {
        cudaEventRecord(ev_join[s], st[s]);
        cudaStreamWaitEvent(0, ev_join[s], 0);
    }

    cudaEventDestroy(ev_fork);
    for (int s = 0; s < NSTR; s++) {
        cudaEventDestroy(ev_join[s]);
        cudaStreamDestroy(st[s]);
    }
}

// round 17
// speedup vs baseline: 1.0163x; 1.0163x over previous
#include <cuda_runtime.h>
#include <cuda_fp16.h>

#define Bq   8
#define Tq   4096
#define DINq 1024
#define DMq  256
#define NCq  157

// ---------------------------------------------------------------------------
// Activations: single fp16 plane, [B, T, C] (K-major for MMA B operand).
// Weights: fp16 hi + lo planes (W = hi + lo, exact to 2^-24).
// GEMM computes W_hi*B + W_lo*B = W*B exactly on fp16-quantized activations.
// ---------------------------------------------------------------------------
__device__ __half g_x  [Bq * Tq * DINq];
__device__ __half g_o  [Bq * Tq * DMq];
__device__ __half g_qkv[Bq * Tq * 3 * DMq];
__device__ __half g_h  [Bq * Tq * DMq];

// Weights: b0w(256x1024), per layer wq|wk|wv|bw (each 256x256), b6w(157x256)
#define W_B0    0
#define W_L0    262144
#define W_PERL  (4 * 65536)
#define W_B6    (262144 + 5 * W_PERL)
#define W_TOTAL (W_B6 + NCq * DMq)
__device__ __half g_wh[W_TOTAL];
__device__ __half g_wl[W_TOTAL];

// ---------------------------------------------------------------------------
// Helpers
// ---------------------------------------------------------------------------
__device__ __forceinline__ unsigned smem_u32(const void* p) {
    unsigned a;
    asm("{ .reg .u64 t; cvta.to.shared.u64 t, %1; cvt.u32.u64 %0, t; }" : "=r"(a) : "l"(p));
    return a;
}
__device__ __forceinline__ void splitw(float v, __half& h, __half& l) {
    h = __float2half_rn(v);
    l = __float2half_rn(v - __half2float(h));
}
__device__ __forceinline__ void ldmat4(unsigned (&r)[4], unsigned addr) {
    asm volatile("ldmatrix.sync.aligned.m8n8.x4.shared.b16 {%0,%1,%2,%3}, [%4];"
                 : "=r"(r[0]), "=r"(r[1]), "=r"(r[2]), "=r"(r[3]) : "r"(addr));
}
__device__ __forceinline__ void mma16816(float (&c)[4], const unsigned (&a)[4],
                                         unsigned b0, unsigned b1) {
    asm volatile(
        "mma.sync.aligned.m16n8k16.row.col.f32.f16.f16.f32 "
        "{%0,%1,%2,%3}, {%4,%5,%6,%7}, {%8,%9}, {%0,%1,%2,%3};"
        : "+f"(c[0]), "+f"(c[1]), "+f"(c[2]), "+f"(c[3])
        : "r"(a[0]), "r"(a[1]), "r"(a[2]), "r"(a[3]), "r"(b0), "r"(b1));
}
// L1-bypass async copy (tiles have zero L1 reuse)
__device__ __forceinline__ void cp16(unsigned saddr, const void* gaddr, int srcsz) {
    asm volatile("cp.async.cg.shared.global [%0], [%1], 16, %2;"
                 :: "r"(saddr), "l"(gaddr), "r"(srcsz) : "memory");
}
#define CP_COMMIT() asm volatile("cp.async.commit_group;" ::: "memory")
#define CP_WAIT1()  asm volatile("cp.async.wait_group 1;" ::: "memory")

// ---------------------------------------------------------------------------
// GEMM: D[o,t] = sum_i W[o,i] * Act[b,t,i]   (split-fp16 x2, mma.sync)
// Block 128(M=o) x 128(N=t), K-SUPERCHUNK 64, 256 threads (8 warps, 4m x 2n),
// warp tile 32x64. 2 superstages x 48KB, single commit per super,
// 64B stride + XOR swizzle.  (R14-proven mainloop, byte-identical)
// EPI: 0 plain -> fp16 [b,t,o] stride OSTR      (qkv)
//      1 +bias -> fp16                          (b0)
//      2 (resid+D+bias)*mask -> fp16            (bottleneck)
//      3 (D+bias)*mask -> fp32 [b,o,t]          (final)
// ---------------------------------------------------------------------------
#define PART     16384              // one plane per super (two 8K k-halves)
#define SSTAGE   49152              // W_hi | W_lo | B
#define SMEM_TOT 98304              // 2 superstages

template <int EPI, int KTOT, int OROWS, int OSTR>
__global__ void __launch_bounds__(256, 2)
gemm_mma(const __half* __restrict__ Whi, const __half* __restrict__ Wlo,
         const __half* __restrict__ Act,
         const float* __restrict__ bias, const float* __restrict__ mask,
         const __half* __restrict__ Resid,
         __half* __restrict__ Out, float* __restrict__ OF)
{
    extern __shared__ char smem[];
    const unsigned sb = smem_u32(smem);
    const int tid  = threadIdx.x;
    const int lane = tid & 31, wid = tid >> 5;
    const int bT = blockIdx.x * 128;
    const int bO = blockIdx.y * 128;
    const int b  = blockIdx.z;
    const int m0 = (wid & 3) * 32;
    const int n0 = (wid >> 2) * 64;

    constexpr bool GUARDA = (OROWS & 127) != 0;
    constexpr int NSUP = KTOT / 64;

    const __half* Bg = Act + ((size_t)b * Tq + bT) * KTOT;

    // ldmatrix per-thread swizzled offsets (64B stride, chunk ^= (row>>1)&3)
    const int raA  = lane & 15;
    const int xorA = (raA >> 1) & 3;
    const int laA[2] = { raA * 64 + ((((lane >> 4)    ) ^ xorA) << 4),
                         raA * 64 + ((((lane >> 4) + 2) ^ xorA) << 4) };
    const int matv = lane >> 3;
    const int rbB  = (lane & 7) + ((matv >> 1) * 8);
    const int xorB = (rbB >> 1) & 3;
    const int lbB[2] = { rbB * 64 + ((((matv & 1)    ) ^ xorB) << 4),
                         rbB * 64 + ((((matv & 1) + 2) ^ xorB) << 4) };

    float acc[2][8][4];
#pragma unroll
    for (int i = 0; i < 2; i++)
#pragma unroll
        for (int j = 0; j < 8; j++)
#pragma unroll
            for (int l = 0; l < 4; l++) acc[i][j][l] = 0.f;

    // ---- superchunk async issue: 12 cp16/thread, ONE commit group ----
    auto issue = [&](int s, int stg) {
        if (s < NSUP) {
            const int k0 = s * 64;
            const unsigned st = sb + stg * SSTAGE;
#pragma unroll
            for (int i = 0; i < 12; i++) {
                const int task = i * 256 + tid;          // 0..3071
                const int plane = task >> 10;            // 0=W.hi 1=W.lo 2=B
                const int q2 = task & 1023;
                const int kh = q2 >> 9;                  // k-half (0/1)
                const int q  = q2 & 511;
                const int row = q >> 2, c = q & 3;
                const unsigned soff = (unsigned)(plane * PART + kh * 8192 +
                                                 row * 64 + ((c ^ ((row >> 1) & 3)) << 4));
                const int kcol = k0 + kh * 32 + c * 8;
                if (plane < 2) {
                    int asz = 16;
                    size_t aoff = (size_t)(bO + row) * KTOT + kcol;
                    if (GUARDA && (bO + row >= OROWS)) { asz = 0; aoff = 0; }
                    cp16(st + soff, (plane ? Wlo : Whi) + aoff, asz);
                } else {
                    cp16(st + soff, Bg + (size_t)row * KTOT + kcol, 16);
                }
            }
        }
        CP_COMMIT();
    };

    issue(0, 0);
    issue(1, 1);

    int cs = 0;
#pragma unroll 1
    for (int s = 0; s < NSUP; s++) {
        CP_WAIT1();
        __syncthreads();

        const unsigned base = sb + cs * SSTAGE;

#pragma unroll
        for (int kk2 = 0; kk2 < 4; kk2++) {
            const int half = kk2 >> 1, kkk = kk2 & 1;
            const unsigned A0_ = base + half * 8192;
            const unsigned A1_ = A0_ + PART;
            const unsigned B_  = A0_ + 2 * PART;
            unsigned ah[2][4], al[2][4];
            ldmat4(ah[0], A0_ + (m0     ) * 64 + laA[kkk]);
            ldmat4(ah[1], A0_ + (m0 + 16) * 64 + laA[kkk]);
            ldmat4(al[0], A1_ + (m0     ) * 64 + laA[kkk]);
            ldmat4(al[1], A1_ + (m0 + 16) * 64 + laA[kkk]);
#pragma unroll
            for (int nt2 = 0; nt2 < 4; nt2++) {
                unsigned bu[4];
                ldmat4(bu, B_ + (n0 + nt2 * 16) * 64 + lbB[kkk]);
                // W_hi * B
                mma16816(acc[0][nt2 * 2 + 0], ah[0], bu[0], bu[1]);
                mma16816(acc[0][nt2 * 2 + 1], ah[0], bu[2], bu[3]);
                mma16816(acc[1][nt2 * 2 + 0], ah[1], bu[0], bu[1]);
                mma16816(acc[1][nt2 * 2 + 1], ah[1], bu[2], bu[3]);
                // W_lo * B
                mma16816(acc[0][nt2 * 2 + 0], al[0], bu[0], bu[1]);
                mma16816(acc[0][nt2 * 2 + 1], al[0], bu[2], bu[3]);
                mma16816(acc[1][nt2 * 2 + 0], al[1], bu[0], bu[1]);
                mma16816(acc[1][nt2 * 2 + 1], al[1], bu[2], bu[3]);
            }
        }

        __syncthreads();           // all warps done reading stage cs
        issue(s + 2, cs);          // refill it
        cs ^= 1;
    }

    // ---- epilogue ----
    const int g = lane >> 2, tig = lane & 3;
#pragma unroll
    for (int mi = 0; mi < 2; mi++) {
#pragma unroll
        for (int pr = 0; pr < 2; pr++) {
            const int o = bO + m0 + mi * 16 + g + pr * 8;
            float bs = 0.f;
            if (EPI >= 1) bs = (!GUARDA || o < OROWS) ? bias[o] : 0.f;
#pragma unroll
            for (int nt = 0; nt < 8; nt++) {
                const int t = bT + n0 + nt * 8 + 2 * tig;
                float v0 = acc[mi][nt][pr * 2 + 0] + bs;
                float v1 = acc[mi][nt][pr * 2 + 1] + bs;
                if (EPI == 3) {
                    if (!GUARDA || o < OROWS) {
                        const float mk0 = mask[(size_t)b * Tq + t];
                        const float mk1 = mask[(size_t)b * Tq + t + 1];
                        *(float2*)(OF + ((size_t)b * OROWS + o) * Tq + t) =
                            make_float2(v0 * mk0, v1 * mk1);
                    }
                } else {
                    const size_t i0 = ((size_t)b * Tq + t) * OSTR + o;
                    if (EPI == 2) {
                        const float mk0 = mask[(size_t)b * Tq + t];
                        const float mk1 = mask[(size_t)b * Tq + t + 1];
                        v0 = (__half2float(Resid[i0])        + v0) * mk0;
                        v1 = (__half2float(Resid[i0 + OSTR]) + v1) * mk1;
                    }
                    Out[i0]        = __float2half_rn(v0);
                    Out[i0 + OSTR] = __float2half_rn(v1);
                }
            }
        }
    }
}

// ---------------------------------------------------------------------------
// x transpose: [B, DIN, T] fp32 -> [B, T, DIN] fp16
// ---------------------------------------------------------------------------
__global__ __launch_bounds__(256)
void xpose_kernel(const float* __restrict__ x, __half* __restrict__ xo)
{
    __shared__ float s[32][33];
    const int t0 = blockIdx.x * 32, i0 = blockIdx.y * 32, b = blockIdx.z;
    const int tx = threadIdx.x & 31, ty = threadIdx.x >> 5;
    const float* xb = x + (size_t)b * DINq * Tq;
#pragma unroll
    for (int kk = 0; kk < 4; kk++)
        s[ty + 8 * kk][tx] = xb[(size_t)(i0 + ty + 8 * kk) * Tq + t0 + tx];
    __syncthreads();
#pragma unroll
    for (int kk = 0; kk < 4; kk++) {
        const size_t idx = ((size_t)b * Tq + t0 + ty + 8 * kk) * DINq + i0 + tx;
        xo[idx] = __float2half_rn(s[tx][ty + 8 * kk]);
    }
}

// ---------------------------------------------------------------------------
// Weight split: 22 fp32 matrices -> fp16 hi/lo
// ---------------------------------------------------------------------------
struct WPtrs { const float* p[22]; };

__global__ __launch_bounds__(256)
void convw_kernel(WPtrs wp, __half* __restrict__ wh, __half* __restrict__ wl)
{
    const int idx = blockIdx.x * 256 + threadIdx.x;
    int off = 0;
#pragma unroll
    for (int m = 0; m < 22; m++) {
        const int sz = (m == 0) ? 262144 : ((m == 21) ? NCq * DMq : 65536);
        if (idx < off + sz) {
            __half h, l;
            splitw(wp.p[m][idx - off], h, l);
            wh[idx] = h; wl[idx] = l;
            return;
        }
        off += sz;
    }
}

// ---------------------------------------------------------------------------
// Dilated 3-tap softmax attention + ReLU on fp16 qkv [B,T,768]
// 8 channels/thread: two uint4 loads per tap, one 16B store.
// ---------------------------------------------------------------------------
__device__ __forceinline__ void load8h(const __half* __restrict__ p, size_t e, float (&o)[8])
{
    const __half2 a = *(const __half2*)(p + e);
    const __half2 c = *(const __half2*)(p + e + 2);
    const __half2 d2 = *(const __half2*)(p + e + 4);
    const __half2 f = *(const __half2*)(p + e + 6);
    o[0] = __low2float(a);  o[1] = __high2float(a);
    o[2] = __low2float(c);  o[3] = __high2float(c);
    o[4] = __low2float(d2); o[5] = __high2float(d2);
    o[6] = __low2float(f);  o[7] = __high2float(f);
}

__device__ __forceinline__ float attn1(float q, float k0, float k1, float k2,
                                       float v0, float v1, float v2)
{
    const float s0 = q * k0, s1 = q * k1, s2 = q * k2;
    const float mx = fmaxf(s0, fmaxf(s1, s2));
    const float e0 = __expf(s0 - mx), e1 = __expf(s1 - mx), e2 = __expf(s2 - mx);
    return fmaxf((e0 * v0 + e1 * v1 + e2 * v2) / (e0 + e1 + e2), 0.f);
}

__global__ __launch_bounds__(256)
void attn_kernel(const __half* __restrict__ qkv, __half* __restrict__ hout, int d)
{
    const size_t gid = (size_t)blockIdx.x * 256 + threadIdx.x;   // 8-channel unit
    const int c8 = (int)(gid & 31);
    const int t  = (int)((gid >> 5) & (Tq - 1));
    const int b  = (int)(gid >> 17);
    const size_t rq = ((size_t)b * Tq + t) * 768 + c8 * 8;
    const long long off = (long long)d * 768;

    float q[8], k1[8], v1[8];
    load8h(qkv, rq,       q);
    load8h(qkv, rq + 256, k1);
    load8h(qkv, rq + 512, v1);
    float k0[8] = {0}, v0[8] = {0}, k2[8] = {0}, v2[8] = {0};
    if (t - d >= 0) { load8h(qkv, rq + 256 - off, k0); load8h(qkv, rq + 512 - off, v0); }
    if (t + d < Tq) { load8h(qkv, rq + 256 + off, k2); load8h(qkv, rq + 512 + off, v2); }

    const size_t e = ((size_t)b * Tq + t) * DMq + c8 * 8;
    unsigned w[4];
#pragma unroll
    for (int c = 0; c < 4; c++) {
        const __half2 p2 = __floats2half2_rn(
            attn1(q[2*c],   k0[2*c],   k1[2*c],   k2[2*c],   v0[2*c],   v1[2*c],   v2[2*c]),
            attn1(q[2*c+1], k0[2*c+1], k1[2*c+1], k2[2*c+1], v0[2*c+1], v1[2*c+1], v2[2*c+1]));
        w[c] = *(const unsigned*)&p2;
    }
    *(uint4*)(hout + e) = make_uint4(w[0], w[1], w[2], w[3]);
}

// ---------------------------------------------------------------------------
// Launch: batch split B=8 -> 4 streams x 2 batches (fork-join capture pattern)
// NOTE: 8 streams trips the harness's device-memory guard (driver-side stream
// resources); 4 is the proven-safe budget.
// ---------------------------------------------------------------------------
#define NSTR 4

extern "C" void kernel_launch(void* const* d_in, const int* in_sizes, int n_in,
                              void* d_out, int out_size)
{
    const float* x    = (const float*)d_in[0];
    const float* mask = (const float*)d_in[1];
    const float* b0b  = (const float*)d_in[3];
    const float* b6b  = (const float*)d_in[30];

    __half *xb, *ob, *qkvb, *hb, *wh, *wl;
    cudaGetSymbolAddress((void**)&xb,   g_x);
    cudaGetSymbolAddress((void**)&ob,   g_o);
    cudaGetSymbolAddress((void**)&qkvb, g_qkv);
    cudaGetSymbolAddress((void**)&hb,   g_h);
    cudaGetSymbolAddress((void**)&wh,   g_wh);
    cudaGetSymbolAddress((void**)&wl,   g_wl);

    cudaFuncSetAttribute(gemm_mma<1, DINq, DMq, DMq>,        cudaFuncAttributeMaxDynamicSharedMemorySize, SMEM_TOT);
    cudaFuncSetAttribute(gemm_mma<0, DMq, 3 * DMq, 3 * DMq>, cudaFuncAttributeMaxDynamicSharedMemorySize, SMEM_TOT);
    cudaFuncSetAttribute(gemm_mma<2, DMq, DMq, DMq>,         cudaFuncAttributeMaxDynamicSharedMemorySize, SMEM_TOT);
    cudaFuncSetAttribute(gemm_mma<3, DMq, NCq, DMq>,         cudaFuncAttributeMaxDynamicSharedMemorySize, SMEM_TOT);

    // split weights (shared by all streams)
    WPtrs wp;
    wp.p[0] = (const float*)d_in[2];
    for (int l = 0; l < 5; l++) {
        wp.p[1 + 4 * l + 0] = (const float*)d_in[4 + 5 * l + 0];
        wp.p[1 + 4 * l + 1] = (const float*)d_in[4 + 5 * l + 1];
        wp.p[1 + 4 * l + 2] = (const float*)d_in[4 + 5 * l + 2];
        wp.p[1 + 4 * l + 3] = (const float*)d_in[4 + 5 * l + 3];
    }
    wp.p[21] = (const float*)d_in[29];
    convw_kernel<<<W_TOTAL / 256, 256>>>(wp, wh, wl);

    // fork worker streams off the main (capture) stream
    cudaStream_t st[NSTR];
    cudaEvent_t ev_fork, ev_join[NSTR];
    for (int s = 0; s < NSTR; s++) cudaStreamCreateWithFlags(&st[s], cudaStreamNonBlocking);
    cudaEventCreateWithFlags(&ev_fork, cudaEventDisableTiming);
    for (int s = 0; s < NSTR; s++) cudaEventCreateWithFlags(&ev_join[s], cudaEventDisableTiming);
    cudaEventRecord(ev_fork, 0);
    for (int s = 0; s < NSTR; s++) cudaStreamWaitEvent(st[s], ev_fork, 0);

    const int dils[5] = {1, 2, 4, 8, 16};
    const int HB = Bq / NSTR;   // 2 batches per stream

    for (int s = 0; s < NSTR; s++) {
        cudaStream_t S = st[s];
        const size_t b0 = (size_t)s * HB;

        const float* x_    = x    + b0 * DINq * Tq;
        const float* mask_ = mask + b0 * Tq;
        __half*      xb_   = xb   + b0 * Tq * DINq;
        __half*      ob_   = ob   + b0 * Tq * DMq;
        __half*      qk_   = qkvb + b0 * Tq * 3 * DMq;
        __half*      hb_   = hb   + b0 * Tq * DMq;
        float*       of_   = (float*)d_out + b0 * NCq * Tq;

        const dim3 thr(256);
        const dim3 g_xp (Tq / 32, DINq / 32, HB);
        const dim3 g_dm (Tq / 128, DMq / 128, HB);
        const dim3 g_qkv(Tq / 128, 3 * DMq / 128, HB);
        const dim3 g_nc (Tq / 128, (NCq + 127) / 128, HB);
        const int  g_at = (HB * Tq * 32) / 256;

        xpose_kernel<<<g_xp, thr, 0, S>>>(x_, xb_);

        gemm_mma<1, DINq, DMq, DMq><<<g_dm, thr, SMEM_TOT, S>>>(
            wh + W_B0, wl + W_B0, xb_, b0b, nullptr, nullptr, ob_, nullptr);

        for (int l = 0; l < 5; l++) {
            const float* bb = (const float*)d_in[4 + 5 * l + 4];
            const int wqkv = W_L0 + l * W_PERL;
            const int bw   = wqkv + 3 * 65536;

            gemm_mma<0, DMq, 3 * DMq, 3 * DMq><<<g_qkv, thr, SMEM_TOT, S>>>(
                wh + wqkv, wl + wqkv, ob_, nullptr, nullptr, nullptr, qk_, nullptr);

            attn_kernel<<<g_at, thr, 0, S>>>(qk_, hb_, dils[l]);

            gemm_mma<2, DMq, DMq, DMq><<<g_dm, thr, SMEM_TOT, S>>>(
                wh + bw, wl + bw, hb_, bb, mask_, ob_, ob_, nullptr);
        }

        gemm_mma<3, DMq, NCq, DMq><<<g_nc, thr, SMEM_TOT, S>>>(
            wh + W_B6, wl + W_B6, ob_, b6b, mask_, nullptr, nullptr, of_);
    }

    // join all streams back into the main stream
    for (int s = 0; s < NSTR; s++) {
        cudaEventRecord(ev_join[s], st[s]);
        cudaStreamWaitEvent(0, ev_join[s], 0);
    }

    cudaEventDestroy(ev_fork);
    for (int s = 0; s < NSTR; s++) {
        cudaEventDestroy(ev_join[s]);
        cudaStreamDestroy(st[s]);
    }
}